// round 11
// baseline (speedup 1.0000x reference)
#include <cuda_runtime.h>
#include <cuda_bf16.h>
#include <cstdint>
#include <math.h>

#define LC   2048
#define CINV 0.35355339059327373f   // 1/(2*sqrt(2))

// Transposed wavelet weights, bf16: [which][k][i*64+o]
__device__ __nv_bfloat16 g_wt[2][(size_t)LC * 4096];

__device__ __forceinline__ float gelu_tanh(float v) {
    float z = 0.7978845608028654f * (v + 0.044715f * v * v * v);
    float t;
    asm("tanh.approx.f32 %0, %1;" : "=f"(t) : "f"(z));
    return 0.5f * v * (1.0f + t);
}

// ---------------------------------------------------------------------------
// Kernel 1: transpose w_approx / w_detail (i,o,l) -> (l, i*64+o), f32 -> bf16
// ---------------------------------------------------------------------------
__global__ void transpose_w_kernel(const float* __restrict__ wA,
                                   const float* __restrict__ wD) {
    __shared__ float tile[32][33];
    const float* src = (blockIdx.z == 0) ? wA : wD;
    __nv_bfloat16* dst = g_wt[blockIdx.z];
    int lbase  = blockIdx.x * 32;
    int iobase = blockIdx.y * 32;
    int tx = threadIdx.x, ty = threadIdx.y;   // block (32, 8)
#pragma unroll
    for (int r = 0; r < 32; r += 8)
        tile[ty + r][tx] = src[(size_t)(iobase + ty + r) * LC + (lbase + tx)];
    __syncthreads();
#pragma unroll
    for (int r = 0; r < 32; r += 8)
        dst[(size_t)(lbase + ty + r) * 4096 + (iobase + tx)] =
            __float2bfloat16(tile[tx][ty + r]);
}

// ---------------------------------------------------------------------------
// Kernel 2: fully fused, 56 KB smem -> 4 CTAs/SM.
// Grid 4096 = (k, half). 256 threads, 16 batches x 8 rows x 64 ch.
// smem: [0,8192)   xs (f32, bl-XOR-swizzled)   — early phases: uv overlay
//       [8192,12288) shrW: bf16 W_t[2][4096] then f32 (W_skip+I)
//       [12288,14336) corr [2][16 b][64 o]
// ---------------------------------------------------------------------------
__global__ __launch_bounds__(256, 4) void fused_kernel(
    const float* __restrict__ x, const float* __restrict__ Ws,
    const float* __restrict__ bsk, float* __restrict__ out)
{
    extern __shared__ float sm[];
    float* xs   = sm;            // 8192 fl (phase>=3); uv overlay (phase<=2)
    float* uv   = sm;            // [2][64 i][17]  = 2176 fl (overlay)
    float* shrW = sm + 8192;     // 4096 fl
    float* corr = sm + 12288;    // 2048 fl

    const int k    = blockIdx.x >> 1;
    const int half = blockIdx.x & 1;
    const int tid  = threadIdx.x;
    const int cg   = (tid & 15) << 2;

    // bias in registers (L1-resident, 256 B table)
    const float4 Bb = __ldg((const float4*)bsk + (tid & 15));

    // ---- Phase 0: W_t bf16 -> shrW region ----
    {
        uint4* dstw = (uint4*)shrW;
#pragma unroll
        for (int it = 0; it < 4; it++) {
            int i = tid + it * 256;             // 0..1023
            int which = i >> 9, idx = i & 511;
            dstw[i] = ((const uint4*)(g_wt[which] + (size_t)k * 4096))[idx];
        }
    }

    // ---- Phase 1: u/v from GMEM (xs not yet loaded; uv overlays xs) ----
#pragma unroll
    for (int it = 0; it < 4; it++) {
        int p  = tid + it * 256;                // 0..1023
        int bl = p >> 6, i = p & 63;
        const float* xp = x + ((size_t)(half * 16 + bl) * 16384
                               + (size_t)k * 8) * 64 + i;
        float e = 0.f, d = 0.f;
#pragma unroll
        for (int j = 0; j < 4; j++) { e += xp[j * 64]; d += xp[(j + 4) * 64]; }
        uv[i * 17 + bl]        = CINV * (e + d);
        uv[1088 + i * 17 + bl] = CINV * (e - d);
    }
    __syncthreads();

    // ---- Phase 2: corrections. thread -> (which, bl, 8 outputs og..og+7) ----
    {
        const int which = tid >> 7;
        const int r  = tid & 127;
        const int bl = r >> 3;
        const int og = (r & 7) * 8;
        const __nv_bfloat16* W = (const __nv_bfloat16*)shrW + which * 4096;
        const float* U = uv + which * 1088;

        float acc[8] = {};
#pragma unroll 8
        for (int i = 0; i < 64; i++) {
            float u = U[i * 17 + bl];
            uint4 wv = *(const uint4*)(W + i * 64 + og);
            float2 w0 = __bfloat1622float2(*(const __nv_bfloat162*)&wv.x);
            float2 w1 = __bfloat1622float2(*(const __nv_bfloat162*)&wv.y);
            float2 w2 = __bfloat1622float2(*(const __nv_bfloat162*)&wv.z);
            float2 w3 = __bfloat1622float2(*(const __nv_bfloat162*)&wv.w);
            acc[0] = fmaf(u, w0.x, acc[0]);
            acc[1] = fmaf(u, w0.y, acc[1]);
            acc[2] = fmaf(u, w1.x, acc[2]);
            acc[3] = fmaf(u, w1.y, acc[3]);
            acc[4] = fmaf(u, w2.x, acc[4]);
            acc[5] = fmaf(u, w2.y, acc[5]);
            acc[6] = fmaf(u, w3.x, acc[6]);
            acc[7] = fmaf(u, w3.y, acc[7]);
        }
        float* cp = corr + which * 1024 + bl * 64 + og;
#pragma unroll
        for (int e = 0; e < 8; e++)
            cp[e] = CINV * (acc[e] - U[(og + e) * 17 + bl]);
    }
    __syncthreads();    // uv dead; shrW(bf16) dead after this point

    // ---- Phase 3: load xs (bl-XOR swizzle) + wsk f32 ----
    {
        const float4* x4  = (const float4*)x;
        float4*       xs4 = (float4*)xs;
#pragma unroll
        for (int it = 0; it < 8; it++) {
            int idx = tid + it * 256;           // 0..2047 float4s
            int bl = idx >> 7, r = idx & 127;   // r = j*16 + c4
            int c4 = (r & 15) ^ (bl & 1);
            int b  = half * 16 + bl;
            xs4[bl * 128 + (r & ~15) + c4] =
                x4[(size_t)b * 262144 + (size_t)k * 128 + r];
        }
#pragma unroll
        for (int it = 0; it < 16; it++) {
            int i = tid + it * 256;             // 0..4095
            float v = Ws[i];
            if ((i >> 6) == (i & 63)) v += 1.0f;
            shrW[i] = v;
        }
    }
    __syncthreads();

    // ---- Phase 4: GEMM + epilogue. 8x4 tile, 2-kk steps, jh-split xv ----
    const int bl = tid >> 4;
    const float* xb  = xs + bl * 512;
    const int   xor4 = (bl & 1) << 2;

    float acc[8][4] = {};
#pragma unroll
    for (int kk = 0; kk < 64; kk += 2) {
        float4 w0 = *(const float4*)(shrW + kk * 64 + cg);
        float4 w1 = *(const float4*)(shrW + (kk + 1) * 64 + cg);
        const int kks = kk ^ xor4;
#pragma unroll
        for (int jh = 0; jh < 2; jh++) {
            float2 xv[4];
#pragma unroll
            for (int j = 0; j < 4; j++)
                xv[j] = *(const float2*)(xb + (jh * 4 + j) * 64 + kks);
#pragma unroll
            for (int j = 0; j < 4; j++) {
                const int jj = jh * 4 + j;
                acc[jj][0] = fmaf(xv[j].x, w0.x, acc[jj][0]);
                acc[jj][0] = fmaf(xv[j].y, w1.x, acc[jj][0]);
                acc[jj][1] = fmaf(xv[j].x, w0.y, acc[jj][1]);
                acc[jj][1] = fmaf(xv[j].y, w1.y, acc[jj][1]);
                acc[jj][2] = fmaf(xv[j].x, w0.z, acc[jj][2]);
                acc[jj][2] = fmaf(xv[j].y, w1.z, acc[jj][2]);
                acc[jj][3] = fmaf(xv[j].x, w0.w, acc[jj][3]);
                acc[jj][3] = fmaf(xv[j].y, w1.w, acc[jj][3]);
            }
        }
    }

    float4 A  = *(const float4*)(corr + bl * 64 + cg);
    float4 Dv = *(const float4*)(corr + 1024 + bl * 64 + cg);
    const int b = half * 16 + bl;
    float* op = out + ((size_t)b * 16384 + (size_t)k * 8) * 64 + cg;
#pragma unroll
    for (int j = 0; j < 8; j++) {
        float sgn = (j < 4) ? 1.f : -1.f;
        float4 rv;
        rv.x = gelu_tanh(acc[j][0] + A.x + sgn * Dv.x + Bb.x);
        rv.y = gelu_tanh(acc[j][1] + A.y + sgn * Dv.y + Bb.y);
        rv.z = gelu_tanh(acc[j][2] + A.z + sgn * Dv.z + Bb.z);
        rv.w = gelu_tanh(acc[j][3] + A.w + sgn * Dv.w + Bb.w);
        *(float4*)(op + j * 64) = rv;
    }
}

extern "C" void kernel_launch(void* const* d_in, const int* in_sizes, int n_in,
                              void* d_out, int out_size) {
    const float* x  = (const float*)d_in[0];   // (32, 16384, 64)
    const float* wA = (const float*)d_in[1];   // (64, 64, 2048)
    const float* wD = (const float*)d_in[2];   // (64, 64, 2048)
    const float* Ws = (const float*)d_in[3];   // (64, 64)
    const float* bs = (const float*)d_in[4];   // (64,)
    float* out = (float*)d_out;

    cudaFuncSetAttribute(fused_kernel,
        cudaFuncAttributeMaxDynamicSharedMemorySize, 57344);

    dim3 tb(32, 8), tg(LC / 32, 4096 / 32, 2);
    transpose_w_kernel<<<tg, tb>>>(wA, wD);

    fused_kernel<<<2 * LC, 256, 57344>>>(x, Ws, bs, out);
}